// round 1
// baseline (speedup 1.0000x reference)
#include <cuda_runtime.h>
#include <mma.h>
#include <cstdint>

using namespace nvcuda;

// Problem constants (fixed by the reference)
constexpr int B   = 256;
constexpr int T   = 256;
constexpr int D   = 72;
constexpr int HID = 512;
constexpr int H   = 1024;
constexpr int H3  = 3 * H;
constexpr int P   = 10;       // to_predict
constexpr int BT  = B * T;    // 65536

// ----------------------------------------------------------------------------
// Device scratch (static globals; no allocation allowed in kernel_launch)
// ----------------------------------------------------------------------------
__device__ float g_buf1  [(size_t)BT * HID];   // lat1 / s1 reuse  (134 MB)
__device__ float g_latent[(size_t)BT * H];     // 268 MB
__device__ float g_xp    [(size_t)BT * H3];    // 805 MB
__device__ float g_eout  [(size_t)BT * H];     // 268 MB
__device__ float g_h     [B * H];
__device__ float g_gh    [B * H3];
__device__ float g_logits[BT];
__device__ float g_wts   [BT];
__device__ float g_hs    [B * H];
__device__ float g_p0    [B * D];
__device__ float g_d1    [B * HID];
__device__ float g_dinp  [B * H];
__device__ float g_gi    [B * H3];
__device__ float g_gh2   [B * H3];
__device__ float g_l1    [B * HID];

// ----------------------------------------------------------------------------
// Generic tf32 WMMA GEMM: C[M,N] = act(A[M,K] * W[N,K]^T + bias)
//   A row-major with row stride lda; W row-major [N,K]; C row stride ldc.
//   Requires: M % 128 == 0, N % 64 == 0, K % 4 == 0. (All shapes here comply.)
// Block tile 128x64, K-step 32, 8 warps each computing a 32x32 sub-tile.
// ----------------------------------------------------------------------------
#define BM 128
#define BN 64
#define BKK 32

struct SMemLoad {
    float As[BM][BKK + 4];   // +4 keeps 16B-aligned ldm (36), reduces conflicts
    float Ws[BN][BKK + 4];
};
union SMemU {
    SMemLoad L;
    float Cs[BM][BN + 4];
};

__global__ void __launch_bounds__(256)
gemm_tf32(const float* __restrict__ A, int lda,
          const float* __restrict__ W,
          const float* __restrict__ bias,
          float* __restrict__ C, int ldc,
          int M, int N, int K, int act)
{
    __shared__ SMemU sm;

    const int bm = blockIdx.y * BM;
    const int bn = blockIdx.x * BN;
    const int tid = threadIdx.x;
    const int warpId = tid >> 5;
    const int wm = warpId & 3;   // 4 warps along M
    const int wn = warpId >> 2;  // 2 warps along N

    wmma::fragment<wmma::accumulator, 16, 16, 8, float> c[2][2];
#pragma unroll
    for (int i = 0; i < 2; i++)
#pragma unroll
        for (int j = 0; j < 2; j++)
            wmma::fill_fragment(c[i][j], 0.0f);

    for (int kk = 0; kk < K; kk += BKK) {
        __syncthreads();
        // ---- load A tile: 128x32 = 1024 float4, 4 per thread ----
#pragma unroll
        for (int i = 0; i < 4; i++) {
            int idx = tid + i * 256;
            int r   = idx >> 3;
            int c4  = (idx & 7) * 4;
            int gk  = kk + c4;
            const float* src = A + (size_t)(bm + r) * lda + gk;
            float4 v = make_float4(0.f, 0.f, 0.f, 0.f);
            if (gk + 4 <= K) {
                v = *reinterpret_cast<const float4*>(src);
            } else {
                float t0 = (gk + 0 < K) ? src[0] : 0.f;
                float t1 = (gk + 1 < K) ? src[1] : 0.f;
                float t2 = (gk + 2 < K) ? src[2] : 0.f;
                float t3 = (gk + 3 < K) ? src[3] : 0.f;
                v = make_float4(t0, t1, t2, t3);
            }
            *reinterpret_cast<float4*>(&sm.L.As[r][c4]) = v;
        }
        // ---- load W tile: 64x32 = 512 float4, 2 per thread ----
#pragma unroll
        for (int i = 0; i < 2; i++) {
            int idx = tid + i * 256;
            int r   = idx >> 3;
            int c4  = (idx & 7) * 4;
            int gk  = kk + c4;
            const float* src = W + (size_t)(bn + r) * K + gk;
            float4 v = make_float4(0.f, 0.f, 0.f, 0.f);
            if (gk + 4 <= K) {
                v = *reinterpret_cast<const float4*>(src);
            } else {
                float t0 = (gk + 0 < K) ? src[0] : 0.f;
                float t1 = (gk + 1 < K) ? src[1] : 0.f;
                float t2 = (gk + 2 < K) ? src[2] : 0.f;
                float t3 = (gk + 3 < K) ? src[3] : 0.f;
                v = make_float4(t0, t1, t2, t3);
            }
            *reinterpret_cast<float4*>(&sm.L.Ws[r][c4]) = v;
        }
        __syncthreads();

#pragma unroll
        for (int ks = 0; ks < 4; ks++) {
            wmma::fragment<wmma::matrix_a, 16, 16, 8, wmma::precision::tf32, wmma::row_major> a[2];
            wmma::fragment<wmma::matrix_b, 16, 16, 8, wmma::precision::tf32, wmma::col_major> b[2];
#pragma unroll
            for (int i = 0; i < 2; i++) {
                wmma::load_matrix_sync(a[i], &sm.L.As[wm * 32 + i * 16][ks * 8], BKK + 4);
#pragma unroll
                for (int e = 0; e < a[i].num_elements; e++)
                    a[i].x[e] = wmma::__float_to_tf32(a[i].x[e]);
            }
#pragma unroll
            for (int j = 0; j < 2; j++) {
                wmma::load_matrix_sync(b[j], &sm.L.Ws[wn * 32 + j * 16][ks * 8], BKK + 4);
#pragma unroll
                for (int e = 0; e < b[j].num_elements; e++)
                    b[j].x[e] = wmma::__float_to_tf32(b[j].x[e]);
            }
#pragma unroll
            for (int i = 0; i < 2; i++)
#pragma unroll
                for (int j = 0; j < 2; j++)
                    wmma::mma_sync(c[i][j], a[i], b[j], c[i][j]);
        }
    }

    __syncthreads();
#pragma unroll
    for (int i = 0; i < 2; i++)
#pragma unroll
        for (int j = 0; j < 2; j++)
            wmma::store_matrix_sync(&sm.Cs[wm * 32 + i * 16][wn * 32 + j * 16],
                                    c[i][j], BN + 4, wmma::mem_row_major);
    __syncthreads();

#pragma unroll
    for (int i = 0; i < 32; i++) {
        int idx = tid + i * 256;
        int r   = idx >> 6;
        int cc  = idx & 63;
        float v = sm.Cs[r][cc];
        if (bias) v += bias[bn + cc];
        if (act == 1) v = fmaxf(v, 0.f);
        C[(size_t)(bm + r) * ldc + bn + cc] = v;
    }
}

// ----------------------------------------------------------------------------
// GRU gate fusion: h_new = (1-z)*n + z*h  (PyTorch gate order r,z,n)
// gi rows strided by gi_stride (encoder reads a time-slice of xp).
// Optionally scatters h_new into a [B,T,H] output at given stride.
// ----------------------------------------------------------------------------
__global__ void gru_gate(const float* __restrict__ gi, size_t gi_stride,
                         const float* __restrict__ gh,
                         float* __restrict__ h,
                         float* __restrict__ out, size_t out_stride)
{
    int idx = blockIdx.x * blockDim.x + threadIdx.x;
    if (idx >= B * H) return;
    int b = idx >> 10;      // /H
    int n = idx & (H - 1);
    const float* gib = gi + (size_t)b * gi_stride;
    const float* ghb = gh + (size_t)b * H3;
    float i_r = gib[n], i_z = gib[n + H], i_n = gib[n + 2 * H];
    float h_r = ghb[n], h_z = ghb[n + H], h_n = ghb[n + 2 * H];
    float r  = 1.f / (1.f + expf(-(i_r + h_r)));
    float z  = 1.f / (1.f + expf(-(i_z + h_z)));
    float nn = tanhf(i_n + r * h_n);
    float hv = h[idx];
    float hnew = (1.f - z) * nn + z * hv;
    h[idx] = hnew;
    if (out) out[(size_t)b * out_stride + n] = hnew;
}

// logits[row] = dot(s1[row,:HID], w2) + b2 ; one warp per row
__global__ void logits_kernel(const float* __restrict__ s1,
                              const float* __restrict__ w2,
                              const float* __restrict__ b2,
                              float* __restrict__ logits)
{
    int row  = blockIdx.x * 8 + (threadIdx.x >> 5);
    int lane = threadIdx.x & 31;
    const float* src = s1 + (size_t)row * HID;
    float acc = 0.f;
    for (int k = lane; k < HID; k += 32) acc += src[k] * w2[k];
#pragma unroll
    for (int o = 16; o > 0; o >>= 1) acc += __shfl_xor_sync(0xffffffffu, acc, o);
    if (lane == 0) logits[row] = acc + b2[0];
}

// softmax over T per batch row; one block (T threads) per b
__global__ void softmax_kernel(const float* __restrict__ logits,
                               float* __restrict__ wts)
{
    __shared__ float sdata[T];
    int b = blockIdx.x, t = threadIdx.x;
    float v = logits[b * T + t];
    sdata[t] = v;
    __syncthreads();
    for (int s = T / 2; s > 0; s >>= 1) {
        if (t < s) sdata[t] = fmaxf(sdata[t], sdata[t + s]);
        __syncthreads();
    }
    float mx = sdata[0];
    __syncthreads();
    float e = expf(v - mx);
    sdata[t] = e;
    __syncthreads();
    for (int s = T / 2; s > 0; s >>= 1) {
        if (t < s) sdata[t] += sdata[t + s];
        __syncthreads();
    }
    wts[b * T + t] = e / sdata[0];
}

// Rep[b,h] = sum_t wts[b,t] * eout[b,t,h]; writes g_hs and (optionally) d_out Rep
__global__ void pool_kernel(const float* __restrict__ eout,
                            const float* __restrict__ wts,
                            float* __restrict__ hs,
                            float* __restrict__ rep_out)
{
    __shared__ float w[T];
    int b = blockIdx.x, tid = threadIdx.x;
    w[tid] = wts[b * T + tid];
    __syncthreads();
    for (int h0 = tid; h0 < H; h0 += blockDim.x) {
        const float* base = eout + (size_t)b * T * H + h0;
        float acc = 0.f;
#pragma unroll 4
        for (int t = 0; t < T; t++) acc += w[t] * base[(size_t)t * H];
        hs[b * H + h0] = acc;
        if (rep_out) rep_out[b * H + h0] = acc;
    }
}

// p0[b,:] = x[b, T-1, :]
__global__ void gather_last(const float* __restrict__ x, float* __restrict__ p0)
{
    int idx = blockIdx.x * blockDim.x + threadIdx.x;
    if (idx >= B * D) return;
    int b = idx / D, dd = idx % D;
    p0[idx] = x[((size_t)b * T + (T - 1)) * D + dd];
}

// pred[m, n<72] = dot(l1[m,:512], w[n,:512]) + bias[n]; out row stride ldc
__global__ void pred_kernel(const float* __restrict__ l1,
                            const float* __restrict__ w,
                            const float* __restrict__ bias,
                            float* __restrict__ out, int ldc)
{
    __shared__ float row[HID];
    int m = blockIdx.x;
    for (int k = threadIdx.x; k < HID; k += blockDim.x)
        row[k] = l1[(size_t)m * HID + k];
    __syncthreads();
    int n = threadIdx.x;
    if (n < D) {
        const float* wr = w + (size_t)n * HID;
        float acc = bias[n];
        for (int k = 0; k < HID; k++) acc += row[k] * wr[k];
        out[(size_t)m * ldc + n] = acc;
    }
}

// ----------------------------------------------------------------------------
// Host driver (graph-capturable: kernels + async memset only)
// ----------------------------------------------------------------------------
static inline void launch_gemm(const float* A, int lda, const float* W,
                               const float* bias, float* C, int ldc,
                               int M, int N, int K, int act)
{
    dim3 grid(N / BN, M / BM);
    gemm_tf32<<<grid, 256>>>(A, lda, W, bias, C, ldc, M, N, K, act);
}

extern "C" void kernel_launch(void* const* d_in, const int* in_sizes, int n_in,
                              void* d_out, int out_size)
{
    // Input order per metadata: x, to_predict, p2l_w1, p2l_b1, p2l_w2, p2l_b2,
    // enc_wih, enc_whh, enc_bih, enc_bhh, dec_wih, dec_whh, dec_bih, dec_bhh,
    // l2p_w1, l2p_b1, l2p_w2, l2p_b2, l2s_w1, l2s_b1, l2s_w2, l2s_b2
    const float* x       = (const float*)d_in[0];
    const float* p2l_w1  = (const float*)d_in[2];
    const float* p2l_b1  = (const float*)d_in[3];
    const float* p2l_w2  = (const float*)d_in[4];
    const float* p2l_b2  = (const float*)d_in[5];
    const float* enc_wih = (const float*)d_in[6];
    const float* enc_whh = (const float*)d_in[7];
    const float* enc_bih = (const float*)d_in[8];
    const float* enc_bhh = (const float*)d_in[9];
    const float* dec_wih = (const float*)d_in[10];
    const float* dec_whh = (const float*)d_in[11];
    const float* dec_bih = (const float*)d_in[12];
    const float* dec_bhh = (const float*)d_in[13];
    const float* l2p_w1  = (const float*)d_in[14];
    const float* l2p_b1  = (const float*)d_in[15];
    const float* l2p_w2  = (const float*)d_in[16];
    const float* l2p_b2  = (const float*)d_in[17];
    const float* l2s_w1  = (const float*)d_in[18];
    const float* l2s_b1  = (const float*)d_in[19];
    const float* l2s_w2  = (const float*)d_in[20];
    const float* l2s_b2  = (const float*)d_in[21];

    float* out = (float*)d_out;
    const int PREDS = B * P * D;             // 184320
    float* rep_out = (out_size >= PREDS + B * H) ? (out + PREDS) : nullptr;

    // Resolve scratch symbols
    float *p_buf1, *p_latent, *p_xp, *p_eout, *p_h, *p_gh, *p_logits, *p_wts,
          *p_hs, *p_p0, *p_d1, *p_dinp, *p_gi, *p_gh2, *p_l1;
    void* tmp;
#define SYM(dst, sym) cudaGetSymbolAddress(&tmp, sym); dst = (float*)tmp;
    SYM(p_buf1, g_buf1)   SYM(p_latent, g_latent) SYM(p_xp, g_xp)
    SYM(p_eout, g_eout)   SYM(p_h, g_h)           SYM(p_gh, g_gh)
    SYM(p_logits, g_logits) SYM(p_wts, g_wts)     SYM(p_hs, g_hs)
    SYM(p_p0, g_p0)       SYM(p_d1, g_d1)         SYM(p_dinp, g_dinp)
    SYM(p_gi, g_gi)       SYM(p_gh2, g_gh2)       SYM(p_l1, g_l1)
#undef SYM

    // ---- par2lat(x): relu chains ----
    launch_gemm(x, D, p2l_w1, p2l_b1, p_buf1, HID, BT, HID, D, 1);
    launch_gemm(p_buf1, HID, p2l_w2, p2l_b2, p_latent, H, BT, H, HID, 1);

    // ---- xp = latent @ enc_wih^T + enc_bih  ([B,T,3H]) ----
    launch_gemm(p_latent, H, enc_wih, enc_bih, p_xp, H3, BT, H3, H, 0);

    // ---- encoder recurrence ----
    cudaMemsetAsync(p_h, 0, (size_t)B * H * sizeof(float));
    const int gate_blocks = (B * H + 255) / 256;
    for (int t = 0; t < T; t++) {
        launch_gemm(p_h, H, enc_whh, enc_bhh, p_gh, H3, B, H3, H, 0);
        gru_gate<<<gate_blocks, 256>>>(p_xp + (size_t)t * H3, (size_t)T * H3,
                                       p_gh, p_h,
                                       p_eout + (size_t)t * H, (size_t)T * H);
    }

    // ---- attention pooling ----
    launch_gemm(p_eout, H, l2s_w1, l2s_b1, p_buf1, HID, BT, HID, H, 1);
    logits_kernel<<<BT / 8, 256>>>(p_buf1, l2s_w2, l2s_b2, p_logits);
    softmax_kernel<<<B, T>>>(p_logits, p_wts);
    pool_kernel<<<B, 256>>>(p_eout, p_wts, p_hs, rep_out);

    // ---- autoregressive decode ----
    gather_last<<<(B * D + 255) / 256, 256>>>(x, p_p0);
    for (int s = 0; s < P; s++) {
        const float* pin = (s == 0) ? p_p0 : (out + (size_t)(s - 1) * D);
        int plda = (s == 0) ? D : (P * D);
        launch_gemm(pin, plda, p2l_w1, p2l_b1, p_d1, HID, B, HID, D, 1);
        launch_gemm(p_d1, HID, p2l_w2, p2l_b2, p_dinp, H, B, H, HID, 1);
        launch_gemm(p_dinp, H, dec_wih, dec_bih, p_gi, H3, B, H3, H, 0);
        launch_gemm(p_hs, H, dec_whh, dec_bhh, p_gh2, H3, B, H3, H, 0);
        gru_gate<<<gate_blocks, 256>>>(p_gi, (size_t)H3, p_gh2, p_hs,
                                       nullptr, 0);
        launch_gemm(p_hs, H, l2p_w1, l2p_b1, p_l1, HID, B, HID, H, 1);
        pred_kernel<<<B, 128>>>(p_l1, l2p_w2, l2p_b2,
                                out + (size_t)s * D, P * D);
    }
}

// round 2
// speedup vs baseline: 1.4214x; 1.4214x over previous
#include <cuda_runtime.h>
#include <mma.h>
#include <cstdint>

using namespace nvcuda;

// Problem constants (fixed by the reference)
constexpr int B   = 256;
constexpr int T   = 256;
constexpr int D   = 72;
constexpr int HID = 512;
constexpr int H   = 1024;
constexpr int H3  = 3 * H;
constexpr int P   = 10;       // to_predict
constexpr int BT  = B * T;    // 65536

// ----------------------------------------------------------------------------
// Device scratch (static globals; no allocation allowed in kernel_launch)
// ----------------------------------------------------------------------------
__device__ float g_buf1  [(size_t)BT * HID];   // lat1 / s1 reuse
__device__ float g_latent[(size_t)BT * H];
__device__ float g_xp    [(size_t)BT * H3];
__device__ float g_eout  [(size_t)BT * H];
__device__ float g_hb0   [B * H];
__device__ float g_hb1   [B * H];
__device__ float g_logits[BT];
__device__ float g_wts   [BT];
__device__ float g_hs    [B * H];
__device__ float g_hs2   [B * H];
__device__ float g_p0    [B * D];
__device__ float g_d1    [B * HID];
__device__ float g_dinp  [B * H];
__device__ float g_gi    [B * H3];
__device__ float g_l1    [B * HID];
__device__ unsigned g_bar_cnt;

// ----------------------------------------------------------------------------
// Generic tf32 WMMA GEMM: C[M,N] = act(A[M,K] * W[N,K]^T + bias)
// (unchanged from round 1 — proven correct)
// ----------------------------------------------------------------------------
#define BM 128
#define BN 64
#define BKK 32

struct SMemLoad {
    float As[BM][BKK + 4];
    float Ws[BN][BKK + 4];
};
union SMemU {
    SMemLoad L;
    float Cs[BM][BN + 4];
};

__global__ void __launch_bounds__(256)
gemm_tf32(const float* __restrict__ A, int lda,
          const float* __restrict__ W,
          const float* __restrict__ bias,
          float* __restrict__ C, int ldc,
          int M, int N, int K, int act)
{
    __shared__ SMemU sm;

    const int bm = blockIdx.y * BM;
    const int bn = blockIdx.x * BN;
    const int tid = threadIdx.x;
    const int warpId = tid >> 5;
    const int wm = warpId & 3;
    const int wn = warpId >> 2;

    wmma::fragment<wmma::accumulator, 16, 16, 8, float> c[2][2];
#pragma unroll
    for (int i = 0; i < 2; i++)
#pragma unroll
        for (int j = 0; j < 2; j++)
            wmma::fill_fragment(c[i][j], 0.0f);

    for (int kk = 0; kk < K; kk += BKK) {
        __syncthreads();
#pragma unroll
        for (int i = 0; i < 4; i++) {
            int idx = tid + i * 256;
            int r   = idx >> 3;
            int c4  = (idx & 7) * 4;
            int gk  = kk + c4;
            const float* src = A + (size_t)(bm + r) * lda + gk;
            float4 v = make_float4(0.f, 0.f, 0.f, 0.f);
            if (gk + 4 <= K) {
                v = *reinterpret_cast<const float4*>(src);
            } else {
                float t0 = (gk + 0 < K) ? src[0] : 0.f;
                float t1 = (gk + 1 < K) ? src[1] : 0.f;
                float t2 = (gk + 2 < K) ? src[2] : 0.f;
                float t3 = (gk + 3 < K) ? src[3] : 0.f;
                v = make_float4(t0, t1, t2, t3);
            }
            *reinterpret_cast<float4*>(&sm.L.As[r][c4]) = v;
        }
#pragma unroll
        for (int i = 0; i < 2; i++) {
            int idx = tid + i * 256;
            int r   = idx >> 3;
            int c4  = (idx & 7) * 4;
            int gk  = kk + c4;
            const float* src = W + (size_t)(bn + r) * K + gk;
            float4 v = make_float4(0.f, 0.f, 0.f, 0.f);
            if (gk + 4 <= K) {
                v = *reinterpret_cast<const float4*>(src);
            } else {
                float t0 = (gk + 0 < K) ? src[0] : 0.f;
                float t1 = (gk + 1 < K) ? src[1] : 0.f;
                float t2 = (gk + 2 < K) ? src[2] : 0.f;
                float t3 = (gk + 3 < K) ? src[3] : 0.f;
                v = make_float4(t0, t1, t2, t3);
            }
            *reinterpret_cast<float4*>(&sm.L.Ws[r][c4]) = v;
        }
        __syncthreads();

#pragma unroll
        for (int ks = 0; ks < 4; ks++) {
            wmma::fragment<wmma::matrix_a, 16, 16, 8, wmma::precision::tf32, wmma::row_major> a[2];
            wmma::fragment<wmma::matrix_b, 16, 16, 8, wmma::precision::tf32, wmma::col_major> b[2];
#pragma unroll
            for (int i = 0; i < 2; i++) {
                wmma::load_matrix_sync(a[i], &sm.L.As[wm * 32 + i * 16][ks * 8], BKK + 4);
#pragma unroll
                for (int e = 0; e < a[i].num_elements; e++)
                    a[i].x[e] = wmma::__float_to_tf32(a[i].x[e]);
            }
#pragma unroll
            for (int j = 0; j < 2; j++) {
                wmma::load_matrix_sync(b[j], &sm.L.Ws[wn * 32 + j * 16][ks * 8], BKK + 4);
#pragma unroll
                for (int e = 0; e < b[j].num_elements; e++)
                    b[j].x[e] = wmma::__float_to_tf32(b[j].x[e]);
            }
#pragma unroll
            for (int i = 0; i < 2; i++)
#pragma unroll
                for (int j = 0; j < 2; j++)
                    wmma::mma_sync(c[i][j], a[i], b[j], c[i][j]);
        }
    }

    __syncthreads();
#pragma unroll
    for (int i = 0; i < 2; i++)
#pragma unroll
        for (int j = 0; j < 2; j++)
            wmma::store_matrix_sync(&sm.Cs[wm * 32 + i * 16][wn * 32 + j * 16],
                                    c[i][j], BN + 4, wmma::mem_row_major);
    __syncthreads();

#pragma unroll
    for (int i = 0; i < 32; i++) {
        int idx = tid + i * 256;
        int r   = idx >> 6;
        int cc  = idx & 63;
        float v = sm.Cs[r][cc];
        if (bias) v += bias[bn + cc];
        if (act == 1) v = fmaxf(v, 0.f);
        C[(size_t)(bm + r) * ldc + bn + cc] = v;
    }
}

// ----------------------------------------------------------------------------
// Persistent fused GRU recurrence.
// Grid = 128 CTAs = 2 b-tiles (128 rows) x 64 n-tiles (16 h-cols, x3 gates).
// Each CTA keeps its 48x1024 slice of Whh resident in SMEM (tf32) for all
// steps. Per step: gh = h @ Whh^T (wmma), fused gate math, write h_new to the
// alternate h buffer (+ optional eout scatter). Grid-wide barrier per step.
// ----------------------------------------------------------------------------
constexpr int RC_NCTA   = 128;
constexpr int RC_BTILE  = 128;   // rows per b-tile (B=256 -> 2 tiles)
constexpr int RC_NCOLS  = 16;    // h-cols per n-tile per gate
constexpr int RC_WROWS  = 48;    // 3 gates * 16
constexpr int RC_KCH    = 64;    // K chunk
constexpr int RC_LDW    = 1028;  // weight smem ld (pad 4)
constexpr int RC_LDA    = 68;    // A smem ld (pad 4)
constexpr int RC_LDG    = 20;    // gate-store smem ld
constexpr int RC_WFLOATS = RC_WROWS * RC_LDW;             // 49344
constexpr int RC_AFLOATS = RC_BTILE * RC_LDA;             // 8704 (>= 3*128*20)
constexpr int RC_SMEM_BYTES = (RC_WFLOATS + RC_AFLOATS) * 4;  // 232192

__device__ __forceinline__ float sigf(float x) { return 1.f / (1.f + expf(-x)); }

__global__ void __launch_bounds__(256, 1)
gru_fused(const float* __restrict__ whh, const float* __restrict__ bhh,
          const float* __restrict__ gi_base, size_t gi_bstride, size_t gi_tstride,
          float* __restrict__ hbuf0, float* __restrict__ hbuf1,
          float* __restrict__ eout, int nsteps)
{
    extern __shared__ float smem[];
    float* Wsm = smem;                 // [48][1028]
    float* Asm = smem + RC_WFLOATS;    // [128][68]; aliased by Gs[3][128][20]
    float* Gsm = Asm;

    const int tid = threadIdx.x;
    const int w   = tid >> 5;          // warp 0..7, owns 16 b-rows
    const int nt  = blockIdx.x & 63;   // n tile
    const int bt  = blockIdx.x >> 6;   // b tile
    const int b0  = bt * RC_BTILE;
    const int n0  = nt * RC_NCOLS;

    // ---- preload weight slab (rows: gate g in {0,1,2}, cols n0..n0+15) ----
    for (int i = tid; i < RC_WROWS * (H / 4); i += 256) {
        int r  = i >> 8;               // 0..47
        int c4 = (i & 255) * 4;
        int g  = r >> 4;
        int nr = r & 15;
        const float4 v = *reinterpret_cast<const float4*>(
            whh + (size_t)(g * H + n0 + nr) * H + c4);
        float* dst = Wsm + r * RC_LDW + c4;
        dst[0] = wmma::__float_to_tf32(v.x);
        dst[1] = wmma::__float_to_tf32(v.y);
        dst[2] = wmma::__float_to_tf32(v.z);
        dst[3] = wmma::__float_to_tf32(v.w);
    }

    for (int t = 0; t < nsteps; t++) {
        // grid barrier between steps (writes of step t-1 -> reads of step t)
        if (t > 0) {
            __syncthreads();
            if (tid == 0) {
                __threadfence();
                atomicAdd(&g_bar_cnt, 1u);
                const unsigned target = (unsigned)t * RC_NCTA;
                while (*(volatile unsigned*)&g_bar_cnt < target) __nanosleep(64);
                __threadfence();
            }
        }

        const float* hread  = (t & 1) ? hbuf1 : hbuf0;
        float*       hwrite = (t & 1) ? hbuf0 : hbuf1;

        wmma::fragment<wmma::accumulator, 16, 16, 8, float> acc[3];
#pragma unroll
        for (int g = 0; g < 3; g++) wmma::fill_fragment(acc[g], 0.0f);

        for (int kk = 0; kk < H; kk += RC_KCH) {
            __syncthreads();   // protect Asm (prev chunk / prev-step Gs reads)
            // load h[b0:b0+128, kk:kk+64] -> Asm (tf32-rounded)
#pragma unroll
            for (int i = 0; i < 8; i++) {
                int idx = tid + i * 256;
                int r   = idx >> 4;
                int c4  = (idx & 15) * 4;
                const float4 v = *reinterpret_cast<const float4*>(
                    hread + (size_t)(b0 + r) * H + kk + c4);
                float* dst = Asm + r * RC_LDA + c4;
                dst[0] = wmma::__float_to_tf32(v.x);
                dst[1] = wmma::__float_to_tf32(v.y);
                dst[2] = wmma::__float_to_tf32(v.z);
                dst[3] = wmma::__float_to_tf32(v.w);
            }
            __syncthreads();

#pragma unroll
            for (int ks = 0; ks < RC_KCH / 8; ks++) {
                wmma::fragment<wmma::matrix_a, 16, 16, 8, wmma::precision::tf32, wmma::row_major> a;
                wmma::load_matrix_sync(a, Asm + (w * 16) * RC_LDA + ks * 8, RC_LDA);
#pragma unroll
                for (int g = 0; g < 3; g++) {
                    wmma::fragment<wmma::matrix_b, 16, 16, 8, wmma::precision::tf32, wmma::col_major> b;
                    wmma::load_matrix_sync(b, Wsm + (g * 16) * RC_LDW + kk + ks * 8, RC_LDW);
                    wmma::mma_sync(acc[g], a, b, acc[g]);
                }
            }
        }

        // ---- epilogue: gates in smem, fused GRU math ----
        __syncthreads();  // all warps done reading Asm before aliasing as Gsm
#pragma unroll
        for (int g = 0; g < 3; g++)
            wmma::store_matrix_sync(Gsm + (g * RC_BTILE + w * 16) * RC_LDG,
                                    acc[g], RC_LDG, wmma::mem_row_major);
        __syncthreads();

        const float* gi_t = gi_base + (size_t)t * gi_tstride;
#pragma unroll
        for (int i = 0; i < 8; i++) {
            int e  = tid + i * 256;
            int bl = e >> 4;
            int nl = e & 15;
            int b  = b0 + bl;
            int nc = n0 + nl;
            float hr = Gsm[(0 * RC_BTILE + bl) * RC_LDG + nl] + bhh[nc];
            float hz = Gsm[(1 * RC_BTILE + bl) * RC_LDG + nl] + bhh[H + nc];
            float hn = Gsm[(2 * RC_BTILE + bl) * RC_LDG + nl] + bhh[2 * H + nc];
            const float* gib = gi_t + (size_t)b * gi_bstride;
            float ir = gib[nc], iz = gib[H + nc], in_ = gib[2 * H + nc];
            float r  = sigf(ir + hr);
            float z  = sigf(iz + hz);
            float nn = tanhf(in_ + r * hn);
            float hv = hread[(size_t)b * H + nc];
            float hnew = (1.f - z) * nn + z * hv;
            hwrite[(size_t)b * H + nc] = hnew;
            if (eout) eout[((size_t)b * T + t) * H + nc] = hnew;
        }
    }
}

// ----------------------------------------------------------------------------
// Small kernels (unchanged)
// ----------------------------------------------------------------------------
__global__ void logits_kernel(const float* __restrict__ s1,
                              const float* __restrict__ w2,
                              const float* __restrict__ b2,
                              float* __restrict__ logits)
{
    int row  = blockIdx.x * 8 + (threadIdx.x >> 5);
    int lane = threadIdx.x & 31;
    const float* src = s1 + (size_t)row * HID;
    float acc = 0.f;
    for (int k = lane; k < HID; k += 32) acc += src[k] * w2[k];
#pragma unroll
    for (int o = 16; o > 0; o >>= 1) acc += __shfl_xor_sync(0xffffffffu, acc, o);
    if (lane == 0) logits[row] = acc + b2[0];
}

__global__ void softmax_kernel(const float* __restrict__ logits,
                               float* __restrict__ wts)
{
    __shared__ float sdata[T];
    int b = blockIdx.x, t = threadIdx.x;
    float v = logits[b * T + t];
    sdata[t] = v;
    __syncthreads();
    for (int s = T / 2; s > 0; s >>= 1) {
        if (t < s) sdata[t] = fmaxf(sdata[t], sdata[t + s]);
        __syncthreads();
    }
    float mx = sdata[0];
    __syncthreads();
    float e = expf(v - mx);
    sdata[t] = e;
    __syncthreads();
    for (int s = T / 2; s > 0; s >>= 1) {
        if (t < s) sdata[t] += sdata[t + s];
        __syncthreads();
    }
    wts[b * T + t] = e / sdata[0];
}

__global__ void pool_kernel(const float* __restrict__ eout,
                            const float* __restrict__ wts,
                            float* __restrict__ hs,
                            float* __restrict__ rep_out)
{
    __shared__ float w[T];
    int b = blockIdx.x, tid = threadIdx.x;
    w[tid] = wts[b * T + tid];
    __syncthreads();
    for (int h0 = tid; h0 < H; h0 += blockDim.x) {
        const float* base = eout + (size_t)b * T * H + h0;
        float acc = 0.f;
#pragma unroll 4
        for (int t = 0; t < T; t++) acc += w[t] * base[(size_t)t * H];
        hs[b * H + h0] = acc;
        if (rep_out) rep_out[b * H + h0] = acc;
    }
}

__global__ void gather_last(const float* __restrict__ x, float* __restrict__ p0)
{
    int idx = blockIdx.x * blockDim.x + threadIdx.x;
    if (idx >= B * D) return;
    int b = idx / D, dd = idx % D;
    p0[idx] = x[((size_t)b * T + (T - 1)) * D + dd];
}

__global__ void pred_kernel(const float* __restrict__ l1,
                            const float* __restrict__ w,
                            const float* __restrict__ bias,
                            float* __restrict__ out, int ldc)
{
    __shared__ float row[HID];
    int m = blockIdx.x;
    for (int k = threadIdx.x; k < HID; k += blockDim.x)
        row[k] = l1[(size_t)m * HID + k];
    __syncthreads();
    int n = threadIdx.x;
    if (n < D) {
        const float* wr = w + (size_t)n * HID;
        float acc = bias[n];
        for (int k = 0; k < HID; k++) acc += row[k] * wr[k];
        out[(size_t)m * ldc + n] = acc;
    }
}

// ----------------------------------------------------------------------------
// Host driver
// ----------------------------------------------------------------------------
static inline void launch_gemm(const float* A, int lda, const float* W,
                               const float* bias, float* C, int ldc,
                               int M, int N, int K, int act)
{
    dim3 grid(N / BN, M / BM);
    gemm_tf32<<<grid, 256>>>(A, lda, W, bias, C, ldc, M, N, K, act);
}

extern "C" void kernel_launch(void* const* d_in, const int* in_sizes, int n_in,
                              void* d_out, int out_size)
{
    const float* x       = (const float*)d_in[0];
    const float* p2l_w1  = (const float*)d_in[2];
    const float* p2l_b1  = (const float*)d_in[3];
    const float* p2l_w2  = (const float*)d_in[4];
    const float* p2l_b2  = (const float*)d_in[5];
    const float* enc_wih = (const float*)d_in[6];
    const float* enc_whh = (const float*)d_in[7];
    const float* enc_bih = (const float*)d_in[8];
    const float* enc_bhh = (const float*)d_in[9];
    const float* dec_wih = (const float*)d_in[10];
    const float* dec_whh = (const float*)d_in[11];
    const float* dec_bih = (const float*)d_in[12];
    const float* dec_bhh = (const float*)d_in[13];
    const float* l2p_w1  = (const float*)d_in[14];
    const float* l2p_b1  = (const float*)d_in[15];
    const float* l2p_w2  = (const float*)d_in[16];
    const float* l2p_b2  = (const float*)d_in[17];
    const float* l2s_w1  = (const float*)d_in[18];
    const float* l2s_b1  = (const float*)d_in[19];
    const float* l2s_w2  = (const float*)d_in[20];
    const float* l2s_b2  = (const float*)d_in[21];

    float* out = (float*)d_out;
    const int PREDS = B * P * D;
    float* rep_out = (out_size >= PREDS + B * H) ? (out + PREDS) : nullptr;

    float *p_buf1, *p_latent, *p_xp, *p_eout, *p_hb0, *p_hb1, *p_logits,
          *p_wts, *p_hs, *p_hs2, *p_p0, *p_d1, *p_dinp, *p_gi, *p_l1;
    unsigned* p_bar;
    void* tmp;
#define SYM(dst, sym) cudaGetSymbolAddress(&tmp, sym); dst = (decltype(dst))tmp;
    SYM(p_buf1, g_buf1)   SYM(p_latent, g_latent) SYM(p_xp, g_xp)
    SYM(p_eout, g_eout)   SYM(p_hb0, g_hb0)       SYM(p_hb1, g_hb1)
    SYM(p_logits, g_logits) SYM(p_wts, g_wts)     SYM(p_hs, g_hs)
    SYM(p_hs2, g_hs2)     SYM(p_p0, g_p0)         SYM(p_d1, g_d1)
    SYM(p_dinp, g_dinp)   SYM(p_gi, g_gi)         SYM(p_l1, g_l1)
    SYM(p_bar, g_bar_cnt)
#undef SYM

    // opt-in to 227KB dynamic smem for the persistent kernel (idempotent)
    cudaFuncSetAttribute(gru_fused, cudaFuncAttributeMaxDynamicSharedMemorySize,
                         RC_SMEM_BYTES);

    // ---- par2lat(x) ----
    launch_gemm(x, D, p2l_w1, p2l_b1, p_buf1, HID, BT, HID, D, 1);
    launch_gemm(p_buf1, HID, p2l_w2, p2l_b2, p_latent, H, BT, H, HID, 1);

    // ---- xp = latent @ enc_wih^T + enc_bih ----
    launch_gemm(p_latent, H, enc_wih, enc_bih, p_xp, H3, BT, H3, H, 0);

    // ---- encoder recurrence: single persistent fused kernel ----
    cudaMemsetAsync(p_hb0, 0, (size_t)B * H * sizeof(float));
    cudaMemsetAsync(p_bar, 0, sizeof(unsigned));
    gru_fused<<<RC_NCTA, 256, RC_SMEM_BYTES>>>(
        enc_whh, enc_bhh, p_xp, (size_t)T * H3, (size_t)H3,
        p_hb0, p_hb1, p_eout, T);

    // ---- attention pooling ----
    launch_gemm(p_eout, H, l2s_w1, l2s_b1, p_buf1, HID, BT, HID, H, 1);
    logits_kernel<<<BT / 8, 256>>>(p_buf1, l2s_w2, l2s_b2, p_logits);
    softmax_kernel<<<B, T>>>(p_logits, p_wts);
    pool_kernel<<<B, 256>>>(p_eout, p_wts, p_hs, rep_out);

    // ---- autoregressive decode ----
    gather_last<<<(B * D + 255) / 256, 256>>>(x, p_p0);
    float* hs_read  = p_hs;
    float* hs_write = p_hs2;
    for (int s = 0; s < P; s++) {
        const float* pin = (s == 0) ? p_p0 : (out + (size_t)(s - 1) * D);
        int plda = (s == 0) ? D : (P * D);
        launch_gemm(pin, plda, p2l_w1, p2l_b1, p_d1, HID, B, HID, D, 1);
        launch_gemm(p_d1, HID, p2l_w2, p2l_b2, p_dinp, H, B, H, HID, 1);
        launch_gemm(p_dinp, H, dec_wih, dec_bih, p_gi, H3, B, H3, H, 0);
        // fused h @ dec_whh^T + GRU gates (1 step, no barrier use)
        gru_fused<<<RC_NCTA, 256, RC_SMEM_BYTES>>>(
            dec_whh, dec_bhh, p_gi, (size_t)H3, 0,
            hs_read, hs_write, nullptr, 1);
        launch_gemm(hs_write, H, l2p_w1, l2p_b1, p_l1, HID, B, HID, H, 1);
        pred_kernel<<<B, 128>>>(p_l1, l2p_w2, l2p_b2,
                                out + (size_t)s * D, P * D);
        float* t2 = hs_read; hs_read = hs_write; hs_write = t2;
    }
}

// round 3
// speedup vs baseline: 1.5781x; 1.1103x over previous
#include <cuda_runtime.h>
#include <mma.h>
#include <cstdint>

using namespace nvcuda;

// Problem constants (fixed by the reference)
constexpr int B   = 256;
constexpr int T   = 256;
constexpr int D   = 72;
constexpr int HID = 512;
constexpr int H   = 1024;
constexpr int H3  = 3 * H;
constexpr int P   = 10;       // to_predict
constexpr int BT  = B * T;    // 65536

// ----------------------------------------------------------------------------
// Device scratch
// ----------------------------------------------------------------------------
__device__ float g_buf1  [(size_t)BT * HID];
__device__ float g_latent[(size_t)BT * H];
__device__ float g_xp    [(size_t)BT * H3];
__device__ float g_eout  [(size_t)BT * H];
__device__ float g_hb0   [B * H];
__device__ float g_hb1   [B * H];
__device__ float g_logits[BT];
__device__ float g_wts   [BT];
__device__ float g_hs    [B * H];
__device__ float g_hs2   [B * H];
__device__ float g_p0    [B * D];
__device__ float g_d1    [B * HID];
__device__ float g_dinp  [B * H];
__device__ float g_gi    [B * H3];
__device__ float g_l1    [B * HID];
__device__ unsigned g_bar_cnt;

// ----------------------------------------------------------------------------
// Pipelined tf32 WMMA GEMM v2: C[M,N] = act(A[M,K] * W[N,K]^T + bias)
// Tile 128x128x32, double-buffered smem, 8 warps (4x2), 32x64 per warp.
// Requires M % 128 == 0, N % 128 == 0. K arbitrary (mult of 4 strides assumed
// for float4 fast path; tail predicated scalar).
// ----------------------------------------------------------------------------
#define BM 128
#define BN 128
#define BK 32
constexpr int GLDS = BK + 4;                                // 36
constexpr int GBUF = (BM + BN) * GLDS;                      // floats per buffer
constexpr int GM_SMEM_BYTES = 2 * GBUF * 4;                 // 73728 B

__device__ __forceinline__ void gm_load_tiles(
    const float* __restrict__ A, int lda,
    const float* __restrict__ W, int K,
    int bm, int bn, int kk, int tid,
    float4 ra[4], float4 rb[4])
{
#pragma unroll
    for (int i = 0; i < 4; i++) {
        int idx = tid + i * 256;
        int r   = idx >> 3;
        int c4  = (idx & 7) * 4;
        int gk  = kk + c4;
        const float* srcA = A + (size_t)(bm + r) * lda + gk;
        const float* srcB = W + (size_t)(bn + r) * K + gk;
        if (gk + 4 <= K) {
            ra[i] = *reinterpret_cast<const float4*>(srcA);
            rb[i] = *reinterpret_cast<const float4*>(srcB);
        } else {
            ra[i].x = (gk + 0 < K) ? srcA[0] : 0.f;
            ra[i].y = (gk + 1 < K) ? srcA[1] : 0.f;
            ra[i].z = (gk + 2 < K) ? srcA[2] : 0.f;
            ra[i].w = (gk + 3 < K) ? srcA[3] : 0.f;
            rb[i].x = (gk + 0 < K) ? srcB[0] : 0.f;
            rb[i].y = (gk + 1 < K) ? srcB[1] : 0.f;
            rb[i].z = (gk + 2 < K) ? srcB[2] : 0.f;
            rb[i].w = (gk + 3 < K) ? srcB[3] : 0.f;
        }
    }
}

__device__ __forceinline__ void gm_store_tiles(
    float* __restrict__ As, float* __restrict__ Bs, int tid,
    const float4 ra[4], const float4 rb[4])
{
#pragma unroll
    for (int i = 0; i < 4; i++) {
        int idx = tid + i * 256;
        int r   = idx >> 3;
        int c4  = (idx & 7) * 4;
        float* da = As + r * GLDS + c4;
        da[0] = wmma::__float_to_tf32(ra[i].x);
        da[1] = wmma::__float_to_tf32(ra[i].y);
        da[2] = wmma::__float_to_tf32(ra[i].z);
        da[3] = wmma::__float_to_tf32(ra[i].w);
        float* db = Bs + r * GLDS + c4;
        db[0] = wmma::__float_to_tf32(rb[i].x);
        db[1] = wmma::__float_to_tf32(rb[i].y);
        db[2] = wmma::__float_to_tf32(rb[i].z);
        db[3] = wmma::__float_to_tf32(rb[i].w);
    }
}

__global__ void __launch_bounds__(256, 1)
gemm_tf32_v2(const float* __restrict__ A, int lda,
             const float* __restrict__ W,
             const float* __restrict__ bias,
             float* __restrict__ C, int ldc,
             int M, int N, int K, int act)
{
    extern __shared__ float sm[];
    float* Abuf[2] = { sm,               sm + GBUF };
    float* Bbuf[2] = { sm + BM * GLDS,   sm + GBUF + BM * GLDS };
    float* Cs = sm;   // alias: [128][132] = 16896 floats < GBUF*2

    const int bm  = blockIdx.y * BM;
    const int bn  = blockIdx.x * BN;
    const int tid = threadIdx.x;
    const int w   = tid >> 5;
    const int wm  = w & 3;    // 4 warps along M, 32 rows each
    const int wn  = w >> 2;   // 2 warps along N, 64 cols each

    wmma::fragment<wmma::accumulator, 16, 16, 8, float> c[2][4];
#pragma unroll
    for (int i = 0; i < 2; i++)
#pragma unroll
        for (int j = 0; j < 4; j++)
            wmma::fill_fragment(c[i][j], 0.0f);

    const int niter = (K + BK - 1) / BK;
    float4 ra[4], rb[4];

    // prologue: tile 0 -> buffer 0
    gm_load_tiles(A, lda, W, K, bm, bn, 0, tid, ra, rb);
    gm_store_tiles(Abuf[0], Bbuf[0], tid, ra, rb);
    __syncthreads();

    for (int it = 0; it < niter; it++) {
        // issue next tile's global loads (latency hides under MMAs below)
        if (it + 1 < niter)
            gm_load_tiles(A, lda, W, K, bm, bn, (it + 1) * BK, tid, ra, rb);

        const float* As = Abuf[it & 1];
        const float* Bs = Bbuf[it & 1];
#pragma unroll
        for (int ks = 0; ks < 4; ks++) {
            wmma::fragment<wmma::matrix_a, 16, 16, 8, wmma::precision::tf32, wmma::row_major> af[2];
            wmma::fragment<wmma::matrix_b, 16, 16, 8, wmma::precision::tf32, wmma::col_major> bf[4];
#pragma unroll
            for (int i = 0; i < 2; i++)
                wmma::load_matrix_sync(af[i], As + (wm * 32 + i * 16) * GLDS + ks * 8, GLDS);
#pragma unroll
            for (int j = 0; j < 4; j++)
                wmma::load_matrix_sync(bf[j], Bs + (wn * 64 + j * 16) * GLDS + ks * 8, GLDS);
#pragma unroll
            for (int i = 0; i < 2; i++)
#pragma unroll
                for (int j = 0; j < 4; j++)
                    wmma::mma_sync(c[i][j], af[i], bf[j], c[i][j]);
        }

        if (it + 1 < niter)
            gm_store_tiles(Abuf[(it + 1) & 1], Bbuf[(it + 1) & 1], tid, ra, rb);
        __syncthreads();
    }

    // epilogue: stage C in smem, fused bias + relu, vectorized store
#pragma unroll
    for (int i = 0; i < 2; i++)
#pragma unroll
        for (int j = 0; j < 4; j++)
            wmma::store_matrix_sync(Cs + (wm * 32 + i * 16) * (BN + 4) + wn * 64 + j * 16,
                                    c[i][j], BN + 4, wmma::mem_row_major);
    __syncthreads();

#pragma unroll
    for (int i = 0; i < 16; i++) {
        int idx4 = tid + i * 256;          // over 128x32 float4s
        int r    = idx4 >> 5;
        int c4   = (idx4 & 31) * 4;
        float4 v = *reinterpret_cast<const float4*>(Cs + r * (BN + 4) + c4);
        if (bias) {
            float4 bv = *reinterpret_cast<const float4*>(bias + bn + c4);
            v.x += bv.x; v.y += bv.y; v.z += bv.z; v.w += bv.w;
        }
        if (act == 1) {
            v.x = fmaxf(v.x, 0.f); v.y = fmaxf(v.y, 0.f);
            v.z = fmaxf(v.z, 0.f); v.w = fmaxf(v.w, 0.f);
        }
        *reinterpret_cast<float4*>(C + (size_t)(bm + r) * ldc + bn + c4) = v;
    }
}

// ----------------------------------------------------------------------------
// Persistent fused GRU recurrence (UNCHANGED from round 2 — proven)
// ----------------------------------------------------------------------------
constexpr int RC_NCTA   = 128;
constexpr int RC_BTILE  = 128;
constexpr int RC_NCOLS  = 16;
constexpr int RC_WROWS  = 48;
constexpr int RC_KCH    = 64;
constexpr int RC_LDW    = 1028;
constexpr int RC_LDA    = 68;
constexpr int RC_LDG    = 20;
constexpr int RC_WFLOATS = RC_WROWS * RC_LDW;
constexpr int RC_AFLOATS = RC_BTILE * RC_LDA;
constexpr int RC_SMEM_BYTES = (RC_WFLOATS + RC_AFLOATS) * 4;

__device__ __forceinline__ float sigf(float x) { return 1.f / (1.f + expf(-x)); }

__global__ void __launch_bounds__(256, 1)
gru_fused(const float* __restrict__ whh, const float* __restrict__ bhh,
          const float* __restrict__ gi_base, size_t gi_bstride, size_t gi_tstride,
          float* __restrict__ hbuf0, float* __restrict__ hbuf1,
          float* __restrict__ eout, int nsteps)
{
    extern __shared__ float smem[];
    float* Wsm = smem;
    float* Asm = smem + RC_WFLOATS;
    float* Gsm = Asm;

    const int tid = threadIdx.x;
    const int w   = tid >> 5;
    const int nt  = blockIdx.x & 63;
    const int bt  = blockIdx.x >> 6;
    const int b0  = bt * RC_BTILE;
    const int n0  = nt * RC_NCOLS;

    for (int i = tid; i < RC_WROWS * (H / 4); i += 256) {
        int r  = i >> 8;
        int c4 = (i & 255) * 4;
        int g  = r >> 4;
        int nr = r & 15;
        const float4 v = *reinterpret_cast<const float4*>(
            whh + (size_t)(g * H + n0 + nr) * H + c4);
        float* dst = Wsm + r * RC_LDW + c4;
        dst[0] = wmma::__float_to_tf32(v.x);
        dst[1] = wmma::__float_to_tf32(v.y);
        dst[2] = wmma::__float_to_tf32(v.z);
        dst[3] = wmma::__float_to_tf32(v.w);
    }

    for (int t = 0; t < nsteps; t++) {
        if (t > 0) {
            __syncthreads();
            if (tid == 0) {
                __threadfence();
                atomicAdd(&g_bar_cnt, 1u);
                const unsigned target = (unsigned)t * RC_NCTA;
                while (*(volatile unsigned*)&g_bar_cnt < target) __nanosleep(64);
                __threadfence();
            }
        }

        const float* hread  = (t & 1) ? hbuf1 : hbuf0;
        float*       hwrite = (t & 1) ? hbuf0 : hbuf1;

        wmma::fragment<wmma::accumulator, 16, 16, 8, float> acc[3];
#pragma unroll
        for (int g = 0; g < 3; g++) wmma::fill_fragment(acc[g], 0.0f);

        for (int kk = 0; kk < H; kk += RC_KCH) {
            __syncthreads();
#pragma unroll
            for (int i = 0; i < 8; i++) {
                int idx = tid + i * 256;
                int r   = idx >> 4;
                int c4  = (idx & 15) * 4;
                const float4 v = *reinterpret_cast<const float4*>(
                    hread + (size_t)(b0 + r) * H + kk + c4);
                float* dst = Asm + r * RC_LDA + c4;
                dst[0] = wmma::__float_to_tf32(v.x);
                dst[1] = wmma::__float_to_tf32(v.y);
                dst[2] = wmma::__float_to_tf32(v.z);
                dst[3] = wmma::__float_to_tf32(v.w);
            }
            __syncthreads();

#pragma unroll
            for (int ks = 0; ks < RC_KCH / 8; ks++) {
                wmma::fragment<wmma::matrix_a, 16, 16, 8, wmma::precision::tf32, wmma::row_major> a;
                wmma::load_matrix_sync(a, Asm + (w * 16) * RC_LDA + ks * 8, RC_LDA);
#pragma unroll
                for (int g = 0; g < 3; g++) {
                    wmma::fragment<wmma::matrix_b, 16, 16, 8, wmma::precision::tf32, wmma::col_major> b;
                    wmma::load_matrix_sync(b, Wsm + (g * 16) * RC_LDW + kk + ks * 8, RC_LDW);
                    wmma::mma_sync(acc[g], a, b, acc[g]);
                }
            }
        }

        __syncthreads();
#pragma unroll
        for (int g = 0; g < 3; g++)
            wmma::store_matrix_sync(Gsm + (g * RC_BTILE + w * 16) * RC_LDG,
                                    acc[g], RC_LDG, wmma::mem_row_major);
        __syncthreads();

        const float* gi_t = gi_base + (size_t)t * gi_tstride;
#pragma unroll
        for (int i = 0; i < 8; i++) {
            int e  = tid + i * 256;
            int bl = e >> 4;
            int nl = e & 15;
            int b  = b0 + bl;
            int nc = n0 + nl;
            float hr = Gsm[(0 * RC_BTILE + bl) * RC_LDG + nl] + bhh[nc];
            float hz = Gsm[(1 * RC_BTILE + bl) * RC_LDG + nl] + bhh[H + nc];
            float hn = Gsm[(2 * RC_BTILE + bl) * RC_LDG + nl] + bhh[2 * H + nc];
            const float* gib = gi_t + (size_t)b * gi_bstride;
            float ir = gib[nc], iz = gib[H + nc], in_ = gib[2 * H + nc];
            float r  = sigf(ir + hr);
            float z  = sigf(iz + hz);
            float nn = tanhf(in_ + r * hn);
            float hv = hread[(size_t)b * H + nc];
            float hnew = (1.f - z) * nn + z * hv;
            hwrite[(size_t)b * H + nc] = hnew;
            if (eout) eout[((size_t)b * T + t) * H + nc] = hnew;
        }
    }
}

// ----------------------------------------------------------------------------
// Small kernels (unchanged)
// ----------------------------------------------------------------------------
__global__ void logits_kernel(const float* __restrict__ s1,
                              const float* __restrict__ w2,
                              const float* __restrict__ b2,
                              float* __restrict__ logits)
{
    int row  = blockIdx.x * 8 + (threadIdx.x >> 5);
    int lane = threadIdx.x & 31;
    const float* src = s1 + (size_t)row * HID;
    float acc = 0.f;
    for (int k = lane; k < HID; k += 32) acc += src[k] * w2[k];
#pragma unroll
    for (int o = 16; o > 0; o >>= 1) acc += __shfl_xor_sync(0xffffffffu, acc, o);
    if (lane == 0) logits[row] = acc + b2[0];
}

__global__ void softmax_kernel(const float* __restrict__ logits,
                               float* __restrict__ wts)
{
    __shared__ float sdata[T];
    int b = blockIdx.x, t = threadIdx.x;
    float v = logits[b * T + t];
    sdata[t] = v;
    __syncthreads();
    for (int s = T / 2; s > 0; s >>= 1) {
        if (t < s) sdata[t] = fmaxf(sdata[t], sdata[t + s]);
        __syncthreads();
    }
    float mx = sdata[0];
    __syncthreads();
    float e = expf(v - mx);
    sdata[t] = e;
    __syncthreads();
    for (int s = T / 2; s > 0; s >>= 1) {
        if (t < s) sdata[t] += sdata[t + s];
        __syncthreads();
    }
    wts[b * T + t] = e / sdata[0];
}

__global__ void pool_kernel(const float* __restrict__ eout,
                            const float* __restrict__ wts,
                            float* __restrict__ hs,
                            float* __restrict__ rep_out)
{
    __shared__ float w[T];
    int b = blockIdx.x, tid = threadIdx.x;
    w[tid] = wts[b * T + tid];
    __syncthreads();
    for (int h0 = tid; h0 < H; h0 += blockDim.x) {
        const float* base = eout + (size_t)b * T * H + h0;
        float acc = 0.f;
#pragma unroll 4
        for (int t = 0; t < T; t++) acc += w[t] * base[(size_t)t * H];
        hs[b * H + h0] = acc;
        if (rep_out) rep_out[b * H + h0] = acc;
    }
}

__global__ void gather_last(const float* __restrict__ x, float* __restrict__ p0)
{
    int idx = blockIdx.x * blockDim.x + threadIdx.x;
    if (idx >= B * D) return;
    int b = idx / D, dd = idx % D;
    p0[idx] = x[((size_t)b * T + (T - 1)) * D + dd];
}

__global__ void pred_kernel(const float* __restrict__ l1,
                            const float* __restrict__ w,
                            const float* __restrict__ bias,
                            float* __restrict__ out, int ldc)
{
    __shared__ float row[HID];
    int m = blockIdx.x;
    for (int k = threadIdx.x; k < HID; k += blockDim.x)
        row[k] = l1[(size_t)m * HID + k];
    __syncthreads();
    int n = threadIdx.x;
    if (n < D) {
        const float* wr = w + (size_t)n * HID;
        float acc = bias[n];
        for (int k = 0; k < HID; k++) acc += row[k] * wr[k];
        out[(size_t)m * ldc + n] = acc;
    }
}

// ----------------------------------------------------------------------------
// Host driver
// ----------------------------------------------------------------------------
static inline void launch_gemm(const float* A, int lda, const float* W,
                               const float* bias, float* C, int ldc,
                               int M, int N, int K, int act)
{
    dim3 grid(N / BN, M / BM);
    gemm_tf32_v2<<<grid, 256, GM_SMEM_BYTES>>>(A, lda, W, bias, C, ldc, M, N, K, act);
}

extern "C" void kernel_launch(void* const* d_in, const int* in_sizes, int n_in,
                              void* d_out, int out_size)
{
    const float* x       = (const float*)d_in[0];
    const float* p2l_w1  = (const float*)d_in[2];
    const float* p2l_b1  = (const float*)d_in[3];
    const float* p2l_w2  = (const float*)d_in[4];
    const float* p2l_b2  = (const float*)d_in[5];
    const float* enc_wih = (const float*)d_in[6];
    const float* enc_whh = (const float*)d_in[7];
    const float* enc_bih = (const float*)d_in[8];
    const float* enc_bhh = (const float*)d_in[9];
    const float* dec_wih = (const float*)d_in[10];
    const float* dec_whh = (const float*)d_in[11];
    const float* dec_bih = (const float*)d_in[12];
    const float* dec_bhh = (const float*)d_in[13];
    const float* l2p_w1  = (const float*)d_in[14];
    const float* l2p_b1  = (const float*)d_in[15];
    const float* l2p_w2  = (const float*)d_in[16];
    const float* l2p_b2  = (const float*)d_in[17];
    const float* l2s_w1  = (const float*)d_in[18];
    const float* l2s_b1  = (const float*)d_in[19];
    const float* l2s_w2  = (const float*)d_in[20];
    const float* l2s_b2  = (const float*)d_in[21];

    float* out = (float*)d_out;
    const int PREDS = B * P * D;
    float* rep_out = (out_size >= PREDS + B * H) ? (out + PREDS) : nullptr;

    float *p_buf1, *p_latent, *p_xp, *p_eout, *p_hb0, *p_hb1, *p_logits,
          *p_wts, *p_hs, *p_hs2, *p_p0, *p_d1, *p_dinp, *p_gi, *p_l1;
    unsigned* p_bar;
    void* tmp;
#define SYM(dst, sym) cudaGetSymbolAddress(&tmp, sym); dst = (decltype(dst))tmp;
    SYM(p_buf1, g_buf1)   SYM(p_latent, g_latent) SYM(p_xp, g_xp)
    SYM(p_eout, g_eout)   SYM(p_hb0, g_hb0)       SYM(p_hb1, g_hb1)
    SYM(p_logits, g_logits) SYM(p_wts, g_wts)     SYM(p_hs, g_hs)
    SYM(p_hs2, g_hs2)     SYM(p_p0, g_p0)         SYM(p_d1, g_d1)
    SYM(p_dinp, g_dinp)   SYM(p_gi, g_gi)         SYM(p_l1, g_l1)
    SYM(p_bar, g_bar_cnt)
#undef SYM

    cudaFuncSetAttribute(gru_fused, cudaFuncAttributeMaxDynamicSharedMemorySize,
                         RC_SMEM_BYTES);
    cudaFuncSetAttribute(gemm_tf32_v2, cudaFuncAttributeMaxDynamicSharedMemorySize,
                         GM_SMEM_BYTES);

    // ---- par2lat(x) ----
    launch_gemm(x, D, p2l_w1, p2l_b1, p_buf1, HID, BT, HID, D, 1);
    launch_gemm(p_buf1, HID, p2l_w2, p2l_b2, p_latent, H, BT, H, HID, 1);

    // ---- xp = latent @ enc_wih^T + enc_bih ----
    launch_gemm(p_latent, H, enc_wih, enc_bih, p_xp, H3, BT, H3, H, 0);

    // ---- encoder recurrence: single persistent fused kernel ----
    cudaMemsetAsync(p_hb0, 0, (size_t)B * H * sizeof(float));
    cudaMemsetAsync(p_bar, 0, sizeof(unsigned));
    gru_fused<<<RC_NCTA, 256, RC_SMEM_BYTES>>>(
        enc_whh, enc_bhh, p_xp, (size_t)T * H3, (size_t)H3,
        p_hb0, p_hb1, p_eout, T);

    // ---- attention pooling ----
    launch_gemm(p_eout, H, l2s_w1, l2s_b1, p_buf1, HID, BT, HID, H, 1);
    logits_kernel<<<BT / 8, 256>>>(p_buf1, l2s_w2, l2s_b2, p_logits);
    softmax_kernel<<<B, T>>>(p_logits, p_wts);
    pool_kernel<<<B, 256>>>(p_eout, p_wts, p_hs, rep_out);

    // ---- autoregressive decode ----
    gather_last<<<(B * D + 255) / 256, 256>>>(x, p_p0);
    float* hs_read  = p_hs;
    float* hs_write = p_hs2;
    for (int s = 0; s < P; s++) {
        const float* pin = (s == 0) ? p_p0 : (out + (size_t)(s - 1) * D);
        int plda = (s == 0) ? D : (P * D);
        launch_gemm(pin, plda, p2l_w1, p2l_b1, p_d1, HID, B, HID, D, 1);
        launch_gemm(p_d1, HID, p2l_w2, p2l_b2, p_dinp, H, B, H, HID, 1);
        launch_gemm(p_dinp, H, dec_wih, dec_bih, p_gi, H3, B, H3, H, 0);
        gru_fused<<<RC_NCTA, 256, RC_SMEM_BYTES>>>(
            dec_whh, dec_bhh, p_gi, (size_t)H3, 0,
            hs_read, hs_write, nullptr, 1);
        launch_gemm(hs_write, H, l2p_w1, l2p_b1, p_l1, HID, B, HID, H, 1);
        pred_kernel<<<B, 128>>>(p_l1, l2p_w2, l2p_b2,
                                out + (size_t)s * D, P * D);
        float* t2 = hs_read; hs_read = hs_write; hs_write = t2;
    }
}